// round 15
// baseline (speedup 1.0000x reference)
#include <cuda_runtime.h>
#include <math.h>
#include <stdint.h>

// Problem constants
#define L_  6
#define B_  16
#define T_  2048
#define D_  768
#define V_  50280
#define R_  96               // L_*B_ rows
#define PW  1572             // ceil(V_/32) bitmap words per batch row

// Per-batch gather-dot GEMM
#define BPB   16             // column blocks per batch
#define CTILE 128            // columns per block
#define NP    (B_ * BPB)     // 256 blocks

// -------- device scratch --------
__device__ unsigned int g_present[B_ * PW];
__device__ int   g_bcount[B_];
__device__ int   g_bidx[B_ * 2048];
__device__ float g_pm[NP * 6];
__device__ float g_ps[NP * 6];
__device__ int   g_pi[NP * 6];
__device__ float g_rownll[R_];
__device__ float g_rowacc[R_];
__device__ int   g_rowvalid[R_];

// online-softmax + first-occurrence-argmax merge
__device__ __forceinline__ void sm_combine(float& m, float& s, int& bi,
                                           float m2, float s2, int bi2) {
    if (m2 > m) {
        s = s * __expf(m - m2) + s2;
        m = m2;
        bi = bi2;
    } else if (m2 == m) {
        s += s2;
        if (bi2 < bi) bi = bi2;
    } else {
        s += s2 * __expf(m2 - m);
    }
}

// -------- small kernels --------
__global__ void zero_present_kernel() {
    int i = blockIdx.x * blockDim.x + threadIdx.x;
    if (i < B_ * PW) g_present[i] = 0u;
}

__global__ void scatter_kernel(const int* __restrict__ ids) {
    int i = blockIdx.x * blockDim.x + threadIdx.x;
    if (i < B_ * T_) {
        int b = i / T_;
        int tok = ids[i];
        if (tok >= 0 && tok < V_)
            atomicOr(&g_present[b * PW + (tok >> 5)], 1u << (tok & 31));
    }
}

// Single-pass per-batch compaction: block b scans present[b] (1572 words)
// with 512 threads (4 words each, thread-contiguous => ascending order).
#define CTHR 512
__global__ void compact_batch() {
    __shared__ int wsum[16];
    const int b = blockIdx.x, t = threadIdx.x;
    const int lane = t & 31, wd = t >> 5;

    unsigned wv[4];
    int cnt = 0;
#pragma unroll
    for (int k = 0; k < 4; k++) {
        int wi = t * 4 + k;
        wv[k] = (wi < PW) ? g_present[b * PW + wi] : 0u;
        cnt += __popc(wv[k]);
    }
    int scan = cnt;                      // inclusive within warp
#pragma unroll
    for (int o = 1; o < 32; o <<= 1) {
        int v = __shfl_up_sync(~0u, scan, o);
        if (lane >= o) scan += v;
    }
    if (lane == 31) wsum[wd] = scan;
    __syncthreads();
    if (wd == 0 && lane < 16) {          // exclusive scan of 16 warp sums
        int v = wsum[lane];
        int sc = v;
#pragma unroll
        for (int o = 1; o < 16; o <<= 1) {
            int u = __shfl_up_sync(0xffffu, sc, o, 16);
            if (lane >= o) sc += u;
        }
        wsum[lane] = sc - v;
    }
    __syncthreads();
    int off = wsum[wd] + scan - cnt;     // global exclusive offset
    if (t == CTHR - 1) g_bcount[b] = wsum[wd] + scan;
#pragma unroll
    for (int k = 0; k < 4; k++) {
        unsigned x = wv[k];
        int base = (t * 4 + k) * 32;
        while (x) {
            int bit = __ffs(x) - 1;
            g_bidx[b * 2048 + off] = base + bit;
            off++;
            x &= x - 1;
        }
    }
}

// ---------------- per-batch gather-dot GEMM + fused softmax/argmax ----------
// Block p: batch b = p/16, column block blk = p%16 -> columns [blk*128, +128).
// Warp handles 4 columns per iteration with 8 lanes per column; each lane
// owns stride-32 float4 chunks of D. Reduction = 3 shfl levels within 8 lanes.
__global__ void __launch_bounds__(256, 1) gemm_dot(const float* __restrict__ x,
                                                   const float* __restrict__ w,
                                                   const int* __restrict__ astarts) {
    __shared__ float s_h[6][D_];
    __shared__ int   s_idx[CTILE];
    __shared__ float s_lg[6][32];
    __shared__ float s_fm[192], s_fs[192];
    __shared__ int   s_fb[192];

    const int p = blockIdx.x;
    const int b = p >> 4, blk = p & 15;
    const int t = threadIdx.x, wid = t >> 5, lane = t & 31;
    const int colg = lane >> 3;          // 0..3 column within warp
    const int sub  = lane & 7;           // 0..7 lane within column
    const int cnt = g_bcount[b];
    const int cstart = blk * CTILE;

    // load h rows straight from x
    int tt = astarts[b] - 1;
    if (tt < 0) tt = 0;
    if (tt >= T_) tt = T_ - 1;
    for (int i = t; i < 6 * (D_ / 4); i += 256) {
        int l = i / (D_ / 4), d4 = i % (D_ / 4);
        reinterpret_cast<float4*>(s_h[l])[d4] =
            reinterpret_cast<const float4*>(x + ((size_t)(l * B_ + b) * T_ + tt) * D_)[d4];
    }
    if (t < CTILE) {
        int gi = cstart + t;
        s_idx[t] = (gi < cnt) ? g_bidx[b * 2048 + gi] : -1;
    }
    __syncthreads();

    // per-thread online state (valid for t < 192: row = t>>5, col = t&31)
    float m1 = -INFINITY, s1 = 0.f;
    int b1 = 0x7fffffff;

#pragma unroll 1
    for (int iter = 0; iter < CTILE / 32; iter++) {
        const int cc = iter * 32 + wid * 4 + colg;
        int v = s_idx[cc];
        const float* wp = w + (size_t)(v < 0 ? 0 : v) * D_;

        float acc[6] = {0.f, 0.f, 0.f, 0.f, 0.f, 0.f};
#pragma unroll
        for (int i = 0; i < 24; i++) {
            int d = i * 32 + sub * 4;
            float4 wv = *reinterpret_cast<const float4*>(wp + d);
#pragma unroll
            for (int l = 0; l < 6; l++) {
                float4 h4 = *reinterpret_cast<const float4*>(&s_h[l][d]);
                acc[l] = fmaf(h4.x, wv.x,
                          fmaf(h4.y, wv.y,
                           fmaf(h4.z, wv.z,
                            fmaf(h4.w, wv.w, acc[l]))));
            }
        }
        // reduce within the 8-lane column group
#pragma unroll
        for (int o = 4; o; o >>= 1)
#pragma unroll
            for (int l = 0; l < 6; l++)
                acc[l] += __shfl_down_sync(~0u, acc[l], o, 8);
        if (sub == 0) {
#pragma unroll
            for (int l = 0; l < 6; l++)
                s_lg[l][wid * 4 + colg] = acc[l];
        }
        __syncthreads();
        if (t < 192) {
            int row = t >> 5, col = t & 31;
            int v2 = s_idx[iter * 32 + col];
            if (v2 >= 0) sm_combine(m1, s1, b1, s_lg[row][col], 1.0f, v2);
        }
        __syncthreads();
    }

    if (t < 192) { s_fm[t] = m1; s_fs[t] = s1; s_fb[t] = b1; }
    __syncthreads();
    if (t < 6) {
        float mm = -INFINITY, ss = 0.f;
        int bb = 0x7fffffff;
        for (int col = 0; col < 32; col++) {
            int k = t * 32 + col;
            sm_combine(mm, ss, bb, s_fm[k], s_fs[k], s_fb[k]);
        }
        g_pm[p * 6 + t] = mm;
        g_ps[p * 6 + t] = ss;
        g_pi[p * 6 + t] = bb;
    }
}

// Per-row: merge BPB block partials + tgt logit dot product (h read from x).
__global__ void reduce_rows_kernel(const float* __restrict__ x,
                                   const float* __restrict__ w,
                                   const int* __restrict__ tgts,
                                   const int* __restrict__ astarts) {
    __shared__ float sdot[128];
    const int r = blockIdx.x;           // r = l*16 + b
    const int t = threadIdx.x;
    const int b = r & (B_ - 1);
    const int l = r >> 4;

    int tt = astarts[b] - 1;
    if (tt < 0) tt = 0;
    if (tt >= T_) tt = T_ - 1;
    const float* hrow = x + ((size_t)r * T_ + tt) * D_;   // r = l*B_+b

    int tgt = tgts[b * L_ + l];
    int tc = (tgt >= 0 && tgt < V_) ? tgt : 0;
    float dot = 0.f;
    for (int d = t; d < D_; d += 128)
        dot += w[(size_t)tc * D_ + d] * hrow[d];
    sdot[t] = dot;
    __syncthreads();
    for (int off = 64; off; off >>= 1) {
        if (t < off) sdot[t] += sdot[t + off];
        __syncthreads();
    }

    if (t == 0) {
        float m = -INFINITY, s = 0.f;
        int bi = 0x7fffffff;
        for (int blk = 0; blk < BPB; blk++) {
            int pp = b * BPB + blk;
            sm_combine(m, s, bi, g_pm[pp * 6 + l], g_ps[pp * 6 + l], g_pi[pp * 6 + l]);
        }
        float lse = m + logf(s);
        float nll = lse - sdot[0];
        int as = astarts[b];
        bool in_range = (as >= 1) && (as < T_);
        bool ptgt = (tgt >= 0 && tgt < V_) &&
                    ((g_present[b * PW + (tgt >> 5)] >> (tgt & 31)) & 1u);
        bool valid = ptgt && in_range;
        int pred = bi;
        g_rownll[r]   = valid ? nll : 0.f;
        g_rowacc[r]   = (valid && pred == tgt) ? 1.f : 0.f;
        g_rowvalid[r] = valid ? 1 : 0;
    }
}

__global__ void finalize_kernel(float* __restrict__ out) {
    if (threadIdx.x == 0) {
        float avg_loss = 0.f, avg_acc = 0.f, final_acc = 0.f;
        int nhas = 0;
        for (int l = 0; l < L_; l++) {
            float cnt = 0.f, sl = 0.f, sa = 0.f;
            for (int b = 0; b < B_; b++) {
                int r = l * B_ + b;
                cnt += (float)g_rowvalid[r];
                sl  += g_rownll[r];
                sa  += g_rowacc[r];
            }
            float denom = fmaxf(cnt, 1.f);
            float ll = sl / denom;
            float la = sa / denom;
            if (cnt > 0.f) { nhas++; avg_loss += ll; avg_acc += la; }
            if (l == L_ - 1) final_acc = la;
        }
        float nv = fmaxf((float)nhas, 1.f);
        out[0] = avg_loss / nv;
        out[1] = avg_acc / nv;
        out[2] = final_acc;
    }
}

extern "C" void kernel_launch(void* const* d_in, const int* in_sizes, int n_in,
                              void* d_out, int out_size) {
    const float* x = nullptr;
    const float* w = nullptr;
    const int* ids = nullptr;
    const int* tgts = nullptr;
    const int* astarts = nullptr;
    for (int i = 0; i < n_in; i++) {
        long sz = (long)in_sizes[i];
        if (sz == (long)L_ * B_ * T_ * D_)      x = (const float*)d_in[i];
        else if (sz == (long)V_ * D_)           w = (const float*)d_in[i];
        else if (sz == (long)B_ * T_)           ids = (const int*)d_in[i];
        else if (sz == (long)B_ * L_)           tgts = (const int*)d_in[i];
        else if (sz == (long)B_)                astarts = (const int*)d_in[i];
    }

    zero_present_kernel<<<(B_ * PW + 255) / 256, 256>>>();
    scatter_kernel<<<(B_ * T_ + 255) / 256, 256>>>(ids);
    compact_batch<<<B_, CTHR>>>();
    gemm_dot<<<NP, 256>>>(x, w, astarts);
    reduce_rows_kernel<<<R_, 128>>>(x, w, tgts, astarts);
    finalize_kernel<<<1, 32>>>((float*)d_out);
}